// round 15
// baseline (speedup 1.0000x reference)
#include <cuda_runtime.h>
#include <cuda_bf16.h>
#include <mma.h>

using namespace nvcuda;

#define N_NODES 16384
#define N_EDGES 524288
#define HID 256
#define HHALF 128
#define R2 2500.0f
#define EPSV 1e-8f
#define NPB 64      // nodes per block in MLP kernel
#define GRIDC 20
#define NCELLS (GRIDC * GRIDC)
#define DCAP 128    // per-node edge bucket capacity (Poisson(32): overflow ~0)
#define CCAP 96     // per-cell node bucket capacity (Poisson(41): overflow ~1e-12)

// wait until all memory ops of the preceding grid are visible (PDL)
__device__ __forceinline__ void pdl_wait() {
    asm volatile("griddepcontrol.wait;" ::: "memory");
}

// ---------------- scratch (device globals, zero-initialized at load) -------
__device__ int    g_deg[N_NODES];          // re-zeroed by k_mlp each call
__device__ int    g_bkt[N_NODES * DCAP];   // edge buckets (8 MB)
__device__ float  g_density[N_NODES];
__device__ float  g_fvar[N_NODES];
__device__ float  g_max[4];                // reset in k_count; [0]=deg,[1]=den,[2]=fvar
__device__ unsigned int g_xh[N_NODES * HHALF];
__device__ float  g_b2rep[16 * HID];       // b2 replicated over 16 rows (C-frag init)
__device__ int    g_cell_cnt[NCELLS];      // re-zeroed by k_mlp block 0
__device__ int    g_node_cell[N_NODES];
__device__ float2 g_cell_xy[NCELLS * CCAP];

__device__ __forceinline__ int cell_of(float v) {
    int c = (int)(v * 0.02f);
    return min(max(c, 0), GRIDC - 1);
}
__device__ __forceinline__ unsigned int pack_bf(float lo, float hi) {
    unsigned int l = (unsigned int)__bfloat16_as_ushort(__float2bfloat16(lo));
    unsigned int h = (unsigned int)__bfloat16_as_ushort(__float2bfloat16(hi));
    return l | (h << 16);
}
// unpack bf16x2 word into an f32 pair and accumulate with ONE packed add
__device__ __forceinline__ void bfacc2(unsigned int u, unsigned long long& acc) {
    unsigned int lo = u << 16;
    unsigned int hi = u & 0xFFFF0000u;
    asm("{\n\t"
        ".reg .b64 p;\n\t"
        "mov.b64 p, {%1, %2};\n\t"
        "add.rn.f32x2 %0, %0, p;\n\t"
        "}" : "+l"(acc) : "r"(lo), "r"(hi));
}
__device__ __forceinline__ float2 upk(unsigned long long v) {
    float2 f;
    asm("mov.b64 {%0, %1}, %2;" : "=f"(f.x), "=f"(f.y) : "l"(v));
    return f;
}

// ---------------- P1: buckets (cells || edges) || bf16 convert || b2rep ----
// blocks [0,64): node cell-buckets; [64,1088): edge buckets; [1088,3136): convert; 3136: b2rep+reset
__global__ void k_count(const float2* __restrict__ coords, const int* __restrict__ row,
                        const int* __restrict__ col, const float4* __restrict__ x4,
                        const float* __restrict__ b2) {
    pdl_wait();
    int b = blockIdx.x, t = threadIdx.x;
    if (b < 64) {
        int i = b * 256 + t;
        float2 p = coords[i];
        int c = cell_of(p.y) * GRIDC + cell_of(p.x);
        g_node_cell[i] = c;
        int slot = atomicAdd(&g_cell_cnt[c], 1);
        g_cell_xy[c * CCAP + slot] = p;
    } else if (b < 64 + 1024) {
        int idx = (b - 64) * 256 + t;
        int2 r2 = ((const int2*)row)[idx];
        int2 c2 = ((const int2*)col)[idx];
        int s0 = atomicAdd(&g_deg[r2.x], 1);
        int s1 = atomicAdd(&g_deg[r2.y], 1);
        g_bkt[r2.x * DCAP + s0] = c2.x;
        g_bkt[r2.y * DCAP + s1] = c2.y;
    } else if (b < 3136) {
        int idx = (b - 1088) * 256 + t;
        float4 a = x4[2 * idx];
        float4 c = x4[2 * idx + 1];
        uint4 o;
        o.x = pack_bf(a.x, a.y);
        o.y = pack_bf(a.z, a.w);
        o.z = pack_bf(c.x, c.y);
        o.w = pack_bf(c.z, c.w);
        ((uint4*)g_xh)[idx] = o;
    } else {
        float v = b2[t];
#pragma unroll
        for (int r = 0; r < 16; r++) g_b2rep[r * HID + t] = v;
        if (t < 4) g_max[t] = 0.0f;          // reset for atomicMax in P2
    }
}

// ---------------- P2: density (cell buckets) || fvar (edge buckets) --------
// blocks [0,64): density (1 node/thread); blocks [64, 64+2048): fvar (1 warp/node)
__global__ void k_den_fvar(const float4* __restrict__ x4, const float2* __restrict__ coords) {
    pdl_wait();
    int b = blockIdx.x, t = threadIdx.x;
    if (b < 64) {
        int i = b * 256 + t;
        float2 p = coords[i];
        int c = g_node_cell[i];
        int cx = c % GRIDC, cy = c / GRIDC;
        int y0 = max(cy - 1, 0), y1 = min(cy + 1, GRIDC - 1);
        int x0 = max(cx - 1, 0), x1 = min(cx + 1, GRIDC - 1);
        int cnt = 0;
        for (int yy = y0; yy <= y1; yy++) {
            for (int xx = x0; xx <= x1; xx++) {
                int cc = yy * GRIDC + xx;
                int e = g_cell_cnt[cc];
                const float2* base = &g_cell_xy[cc * CCAP];
                for (int k = 0; k < e; k++) {
                    float2 q = base[k];
                    float dx = p.x - q.x;
                    float dy = p.y - q.y;
                    cnt += (fmaf(dx, dx, dy * dy) <= R2) ? 1 : 0;
                }
            }
        }
        g_density[i] = (float)cnt;
        float v = (float)(cnt - 1);
#pragma unroll
        for (int off = 16; off > 0; off >>= 1)
            v = fmaxf(v, __shfl_down_sync(0xFFFFFFFFu, v, off));
        __shared__ float wm[8];
        if ((t & 31) == 0) wm[t >> 5] = v;
        __syncthreads();
        if (t == 0) {
            float m = wm[0];
#pragma unroll
            for (int w = 1; w < 8; w++) m = fmaxf(m, wm[w]);
            atomicMax((int*)&g_max[1], __float_as_int(m));
        }
    } else {
        int warp = t >> 5, lane = t & 31;
        int n = (b - 64) * 8 + warp;
        int deg = g_deg[n];
        const int* bkt = &g_bkt[n * DCAP];
        const uint4* xh = (const uint4*)g_xh;

        unsigned long long a01 = 0, a23 = 0, a45 = 0, a67 = 0;
        int e = 0;
        for (; e + 8 <= deg; e += 8) {
            int cc[8];
#pragma unroll
            for (int k = 0; k < 8; k++) cc[k] = bkt[e + k];
            uint4 vv[8];
#pragma unroll
            for (int k = 0; k < 8; k++) vv[k] = xh[cc[k] * 32 + lane];
#pragma unroll
            for (int k = 0; k < 8; k++) {
                bfacc2(vv[k].x, a01); bfacc2(vv[k].y, a23);
                bfacc2(vv[k].z, a45); bfacc2(vv[k].w, a67);
            }
        }
        for (; e < deg; e++) {
            uint4 v = xh[bkt[e] * 32 + lane];
            bfacc2(v.x, a01); bfacc2(v.y, a23); bfacc2(v.z, a45); bfacc2(v.w, a67);
        }
        float2 s01 = upk(a01), s23 = upk(a23), s45 = upk(a45), s67 = upk(a67);

        float inv = 1.0f / (float)(deg > 1 ? deg : 1);
        float4 xa = x4[n * 64 + lane * 2];
        float4 xb = x4[n * 64 + lane * 2 + 1];
        float d0 = xa.x - s01.x * inv, d1 = xa.y - s01.y * inv;
        float d2 = xa.z - s23.x * inv, d3 = xa.w - s23.y * inv;
        float d4 = xb.x - s45.x * inv, d5 = xb.y - s45.y * inv;
        float d6 = xb.z - s67.x * inv, d7 = xb.w - s67.y * inv;
        float local = fmaf(d0, d0, fmaf(d1, d1, fmaf(d2, d2, d3 * d3)))
                    + fmaf(d4, d4, fmaf(d5, d5, fmaf(d6, d6, d7 * d7)));
#pragma unroll
        for (int off = 16; off > 0; off >>= 1)
            local += __shfl_down_sync(0xFFFFFFFFu, local, off);

        __shared__ float fv8[8];
        __shared__ int   dg8[8];
        if (lane == 0) {
            float fv = sqrtf(local);
            g_fvar[n] = fv;
            fv8[warp] = fv;
            dg8[warp] = deg;
        }
        __syncthreads();
        if (t == 0) {
            float m = fv8[0];
            int dm = dg8[0];
#pragma unroll
            for (int w = 1; w < 8; w++) { m = fmaxf(m, fv8[w]); dm = max(dm, dg8[w]); }
            atomicMax((int*)&g_max[2], __float_as_int(m));
            atomicMax((int*)&g_max[0], __float_as_int((float)dm));
        }
    }
}

// ---------------- P3: MLP — tf32 WMMA, B fragments from global (L1-served) --
__global__ void k_mlp(const float* __restrict__ w1, const float* __restrict__ b1,
                      const float* __restrict__ w2, float* __restrict__ out) {
    pdl_wait();
    __shared__ float s_feats[NPB][3];
    __shared__ __align__(16) float s_hid[NPB][HHALF];   // tf32-rounded at store
    int t = threadIdx.x;
    int n0 = blockIdx.x * NPB;

    if (t < NPB) {
        int n = n0 + t;
        float invd   = 1.0f / (g_max[0] + EPSV);
        float invden = 1.0f / (g_max[1] + EPSV);
        float invf   = 1.0f / (g_max[2] + EPSV);
        s_feats[t][0] = (float)g_deg[n] * invd;
        s_feats[t][1] = (g_density[n] - 1.0f) * invden;
        s_feats[t][2] = g_fvar[n] * invf;
        g_deg[n] = 0;                       // recycle for next call (own node)
    }
    if (blockIdx.x == 0) {                  // recycle cells (mlp never reads them)
        for (int i = t; i < NCELLS; i += 256) g_cell_cnt[i] = 0;
    }
    __syncthreads();

    for (int idx = t; idx < NPB * HHALF; idx += 256) {
        int j = idx & (HHALF - 1);
        int node = idx >> 7;
        float v = b1[j]
                + s_feats[node][0] * w1[j]
                + s_feats[node][1] * w1[HHALF + j]
                + s_feats[node][2] * w1[2 * HHALF + j];
        s_hid[node][j] = wmma::__float_to_tf32(fmaxf(v, 0.0f));
    }
    __syncthreads();

    int warp = t >> 5;
    int msub = warp & 3;
    int nbase = (warp >> 2) * 8;

    wmma::fragment<wmma::accumulator, 16, 16, 8, float> cf[8];
#pragma unroll
    for (int i = 0; i < 8; i++)
        wmma::load_matrix_sync(cf[i], g_b2rep + (nbase + i) * 16, HID, wmma::mem_row_major);

    for (int k = 0; k < 16; k++) {
        wmma::fragment<wmma::matrix_a, 16, 16, 8, wmma::precision::tf32, wmma::row_major> af;
        wmma::load_matrix_sync(af, &s_hid[msub * 16][k * 8], HHALF);
#pragma unroll
        for (int i = 0; i < 8; i++) {
            wmma::fragment<wmma::matrix_b, 16, 16, 8, wmma::precision::tf32, wmma::row_major> bf;
            wmma::load_matrix_sync(bf, w2 + (k * 8) * HID + (nbase + i) * 16, HID);
#pragma unroll
            for (int e = 0; e < bf.num_elements; e++) bf.x[e] = wmma::__float_to_tf32(bf.x[e]);
            wmma::mma_sync(cf[i], af, bf, cf[i]);
        }
    }
#pragma unroll
    for (int i = 0; i < 8; i++)
        wmma::store_matrix_sync(out + (n0 + msub * 16) * HID + (nbase + i) * 16,
                                cf[i], HID, wmma::mem_row_major);
}

// ---------------- launch (PDL-chained, 3 kernels) ---------------------------
template <typename K, typename... Args>
static void pdl_launch(K kern, dim3 grid, dim3 block, Args... args) {
    cudaLaunchConfig_t cfg = {};
    cfg.gridDim = grid;
    cfg.blockDim = block;
    cudaLaunchAttribute attr[1];
    attr[0].id = cudaLaunchAttributeProgrammaticStreamSerialization;
    attr[0].val.programmaticStreamSerializationAllowed = 1;
    cfg.attrs = attr;
    cfg.numAttrs = 1;
    cudaLaunchKernelEx(&cfg, kern, args...);
}

extern "C" void kernel_launch(void* const* d_in, const int* in_sizes, int n_in,
                              void* d_out, int out_size) {
    const float*  x      = (const float*)d_in[0];
    const int*    ei     = (const int*)d_in[1];
    const float2* coords = (const float2*)d_in[2];
    const float*  w1     = (const float*)d_in[3];
    const float*  b1     = (const float*)d_in[4];
    const float*  w2     = (const float*)d_in[5];
    const float*  b2     = (const float*)d_in[6];
    float*        out    = (float*)d_out;

    const int* row = ei;
    const int* col = ei + N_EDGES;

    pdl_launch(k_count, dim3(3137), dim3(256), coords, row, col, (const float4*)x, b2);
    pdl_launch(k_den_fvar, dim3(64 + 2048), dim3(256), (const float4*)x, coords);
    pdl_launch(k_mlp, dim3(N_NODES / NPB), dim3(256), w1, b1, w2, out);
}

// round 16
// speedup vs baseline: 2.0987x; 2.0987x over previous
#include <cuda_runtime.h>
#include <cuda_bf16.h>
#include <mma.h>

using namespace nvcuda;

#define N_NODES 16384
#define N_EDGES 524288
#define HID 256
#define HHALF 128
#define R2 2500.0f
#define EPSV 1e-8f
#define NPB 64      // nodes per block in MLP kernel
#define GRIDC 20
#define NCELLS (GRIDC * GRIDC)
#define DCAP 128    // per-node edge bucket capacity (Poisson(32): overflow ~0)

// wait until all memory ops of the preceding grid are visible (PDL)
__device__ __forceinline__ void pdl_wait() {
    asm volatile("griddepcontrol.wait;" ::: "memory");
}

// ---------------- scratch (device globals, zero-initialized at load) -------
__device__ int    g_deg[N_NODES];          // re-zeroed by k_mlp each call
__device__ int    g_bkt[N_NODES * DCAP];   // edge buckets (8 MB)
__device__ float  g_density[N_NODES];
__device__ float  g_fvar[N_NODES];
__device__ float  g_max[4];                // reset in k_count tail block
__device__ unsigned int g_xh[N_NODES * HHALF];
__device__ float  g_b2rep[16 * HID];       // b2 replicated over 16 rows (C-frag init)
__device__ int    g_cell_cnt[NCELLS];      // re-zeroed by k_mlp block 0
__device__ int    g_cell_fill[NCELLS];     // re-zeroed by k_mlp block 0
__device__ int    g_cell_ptr[NCELLS + 1];
__device__ int    g_node_cell[N_NODES];
__device__ float2 g_sorted_xy[N_NODES];
__device__ int    g_sorted_id[N_NODES];

__device__ __forceinline__ int cell_of(float v) {
    int c = (int)(v * 0.02f);
    return min(max(c, 0), GRIDC - 1);
}
__device__ __forceinline__ unsigned int pack_bf(float lo, float hi) {
    unsigned int l = (unsigned int)__bfloat16_as_ushort(__float2bfloat16(lo));
    unsigned int h = (unsigned int)__bfloat16_as_ushort(__float2bfloat16(hi));
    return l | (h << 16);
}
// unpack bf16x2 word into an f32 pair and accumulate with ONE packed add
__device__ __forceinline__ void bfacc2(unsigned int u, unsigned long long& acc) {
    unsigned int lo = u << 16;
    unsigned int hi = u & 0xFFFF0000u;
    asm("{\n\t"
        ".reg .b64 p;\n\t"
        "mov.b64 p, {%1, %2};\n\t"
        "add.rn.f32x2 %0, %0, p;\n\t"
        "}" : "+l"(acc) : "r"(lo), "r"(hi));
}
__device__ __forceinline__ float2 upk(unsigned long long v) {
    float2 f;
    asm("mov.b64 {%0, %1}, %2;" : "=f"(f.x), "=f"(f.y) : "l"(v));
    return f;
}

// ---------------- P1: cell hist || edge buckets || bf16 convert || b2rep ---
// blocks [0,64): cell hist; [64,1088): edge buckets; [1088,3136): convert; 3136: b2rep+reset
__global__ void k_count(const float2* __restrict__ coords, const int* __restrict__ row,
                        const int* __restrict__ col, const float4* __restrict__ x4,
                        const float* __restrict__ b2) {
    pdl_wait();
    int b = blockIdx.x, t = threadIdx.x;
    if (b < 64) {
        int i = b * 256 + t;
        float2 p = coords[i];
        int c = cell_of(p.y) * GRIDC + cell_of(p.x);
        g_node_cell[i] = c;
        atomicAdd(&g_cell_cnt[c], 1);
    } else if (b < 64 + 1024) {
        int idx = (b - 64) * 256 + t;
        int2 r2 = ((const int2*)row)[idx];
        int2 c2 = ((const int2*)col)[idx];
        int s0 = atomicAdd(&g_deg[r2.x], 1);
        int s1 = atomicAdd(&g_deg[r2.y], 1);
        g_bkt[r2.x * DCAP + s0] = c2.x;
        g_bkt[r2.y * DCAP + s1] = c2.y;
    } else if (b < 3136) {
        int idx = (b - 1088) * 256 + t;
        float4 a = x4[2 * idx];
        float4 c = x4[2 * idx + 1];
        uint4 o;
        o.x = pack_bf(a.x, a.y);
        o.y = pack_bf(a.z, a.w);
        o.z = pack_bf(c.x, c.y);
        o.w = pack_bf(c.z, c.w);
        ((uint4*)g_xh)[idx] = o;
    } else {
        float v = b2[t];
#pragma unroll
        for (int r = 0; r < 16; r++) g_b2rep[r * HID + t] = v;
        if (t < 4) g_max[t] = 0.0f;          // reset for atomicMax in P4
    }
}

// ---------------- P2: exclusive scan over 400 cell counts (1 block) --------
__global__ void k_scan_cells() {
    pdl_wait();
    int t = threadIdx.x;
    int lane = t & 31, warp = t >> 5;
    int v = (t < NCELLS) ? g_cell_cnt[t] : 0;
    int s = v;
#pragma unroll
    for (int o = 1; o < 32; o <<= 1) {
        int u = __shfl_up_sync(0xFFFFFFFFu, s, o);
        if (lane >= o) s += u;
    }
    __shared__ int wt[16];
    if (lane == 31) wt[warp] = s;
    __syncthreads();
    if (warp == 0 && lane < 16) {
        int w = wt[lane];
#pragma unroll
        for (int o = 1; o < 16; o <<= 1) {
            int u = __shfl_up_sync(0xFFFFu, w, o);
            if (lane >= o) w += u;
        }
        wt[lane] = w;
    }
    __syncthreads();
    int incl = s + (warp > 0 ? wt[warp - 1] : 0);
    if (t < NCELLS) g_cell_ptr[t] = incl - v;
    if (t == NCELLS - 1) g_cell_ptr[NCELLS] = incl;
}

// ---------------- P3: bin fill (sorted-by-cell array for density locality) -
__global__ void k_fills(const float2* __restrict__ coords) {
    pdl_wait();
    int i = blockIdx.x * 256 + threadIdx.x;
    int c = g_node_cell[i];
    int pos = g_cell_ptr[c] + atomicAdd(&g_cell_fill[c], 1);
    g_sorted_xy[pos] = coords[i];
    g_sorted_id[pos] = i;
}

// ---------------- P4: density (sorted spans) || fvar (edge buckets) --------
// blocks [0,64): density (1 node/thread); blocks [64, 64+2048): fvar (1 warp/node)
__global__ void k_den_fvar(const float4* __restrict__ x4) {
    pdl_wait();
    int b = blockIdx.x, t = threadIdx.x;
    if (b < 64) {
        int i = b * 256 + t;
        float2 p = g_sorted_xy[i];
        int cx = cell_of(p.x), cy = cell_of(p.y);
        int y0 = max(cy - 1, 0), y1 = min(cy + 1, GRIDC - 1);
        int x0 = max(cx - 1, 0), x1 = min(cx + 1, GRIDC - 1);
        int cnt = 0;
        for (int yy = y0; yy <= y1; yy++) {
            int bb = g_cell_ptr[yy * GRIDC + x0];
            int ee = g_cell_ptr[yy * GRIDC + x1 + 1];
            for (int k = bb; k < ee; k++) {
                float2 q = g_sorted_xy[k];
                float dx = p.x - q.x;
                float dy = p.y - q.y;
                cnt += (fmaf(dx, dx, dy * dy) <= R2) ? 1 : 0;
            }
        }
        g_density[g_sorted_id[i]] = (float)cnt;
        float v = (float)(cnt - 1);
#pragma unroll
        for (int off = 16; off > 0; off >>= 1)
            v = fmaxf(v, __shfl_down_sync(0xFFFFFFFFu, v, off));
        __shared__ float wm[8];
        if ((t & 31) == 0) wm[t >> 5] = v;
        __syncthreads();
        if (t == 0) {
            float m = wm[0];
#pragma unroll
            for (int w = 1; w < 8; w++) m = fmaxf(m, wm[w]);
            atomicMax((int*)&g_max[1], __float_as_int(m));
        }
    } else {
        int warp = t >> 5, lane = t & 31;
        int n = (b - 64) * 8 + warp;
        int deg = g_deg[n];
        const int* bkt = &g_bkt[n * DCAP];
        const uint4* xh = (const uint4*)g_xh;

        unsigned long long a01 = 0, a23 = 0, a45 = 0, a67 = 0;
        int e = 0;
        for (; e + 8 <= deg; e += 8) {
            int cc[8];
#pragma unroll
            for (int k = 0; k < 8; k++) cc[k] = bkt[e + k];
            uint4 vv[8];
#pragma unroll
            for (int k = 0; k < 8; k++) vv[k] = xh[cc[k] * 32 + lane];
#pragma unroll
            for (int k = 0; k < 8; k++) {
                bfacc2(vv[k].x, a01); bfacc2(vv[k].y, a23);
                bfacc2(vv[k].z, a45); bfacc2(vv[k].w, a67);
            }
        }
        for (; e < deg; e++) {
            uint4 v = xh[bkt[e] * 32 + lane];
            bfacc2(v.x, a01); bfacc2(v.y, a23); bfacc2(v.z, a45); bfacc2(v.w, a67);
        }
        float2 s01 = upk(a01), s23 = upk(a23), s45 = upk(a45), s67 = upk(a67);

        float inv = 1.0f / (float)(deg > 1 ? deg : 1);
        float4 xa = x4[n * 64 + lane * 2];
        float4 xb = x4[n * 64 + lane * 2 + 1];
        float d0 = xa.x - s01.x * inv, d1 = xa.y - s01.y * inv;
        float d2 = xa.z - s23.x * inv, d3 = xa.w - s23.y * inv;
        float d4 = xb.x - s45.x * inv, d5 = xb.y - s45.y * inv;
        float d6 = xb.z - s67.x * inv, d7 = xb.w - s67.y * inv;
        float local = fmaf(d0, d0, fmaf(d1, d1, fmaf(d2, d2, d3 * d3)))
                    + fmaf(d4, d4, fmaf(d5, d5, fmaf(d6, d6, d7 * d7)));
#pragma unroll
        for (int off = 16; off > 0; off >>= 1)
            local += __shfl_down_sync(0xFFFFFFFFu, local, off);

        __shared__ float fv8[8];
        __shared__ int   dg8[8];
        if (lane == 0) {
            float fv = sqrtf(local);
            g_fvar[n] = fv;
            fv8[warp] = fv;
            dg8[warp] = deg;
        }
        __syncthreads();
        if (t == 0) {
            float m = fv8[0];
            int dm = dg8[0];
#pragma unroll
            for (int w = 1; w < 8; w++) { m = fmaxf(m, fv8[w]); dm = max(dm, dg8[w]); }
            atomicMax((int*)&g_max[2], __float_as_int(m));
            atomicMax((int*)&g_max[0], __float_as_int((float)dm));
        }
    }
}

// ---------------- P5: MLP — tf32 WMMA, B fragments from global (L1-served) --
__global__ void k_mlp(const float* __restrict__ w1, const float* __restrict__ b1,
                      const float* __restrict__ w2, float* __restrict__ out) {
    pdl_wait();
    __shared__ float s_feats[NPB][3];
    __shared__ __align__(16) float s_hid[NPB][HHALF];   // tf32-rounded at store
    int t = threadIdx.x;
    int n0 = blockIdx.x * NPB;

    if (t < NPB) {
        int n = n0 + t;
        float invd   = 1.0f / (g_max[0] + EPSV);
        float invden = 1.0f / (g_max[1] + EPSV);
        float invf   = 1.0f / (g_max[2] + EPSV);
        s_feats[t][0] = (float)g_deg[n] * invd;
        s_feats[t][1] = (g_density[n] - 1.0f) * invden;
        s_feats[t][2] = g_fvar[n] * invf;
        g_deg[n] = 0;                       // recycle for next call (own node)
    }
    if (blockIdx.x == 0) {                  // recycle cells (mlp never reads them)
        for (int i = t; i < NCELLS; i += 256) { g_cell_cnt[i] = 0; g_cell_fill[i] = 0; }
    }
    __syncthreads();

    for (int idx = t; idx < NPB * HHALF; idx += 256) {
        int j = idx & (HHALF - 1);
        int node = idx >> 7;
        float v = b1[j]
                + s_feats[node][0] * w1[j]
                + s_feats[node][1] * w1[HHALF + j]
                + s_feats[node][2] * w1[2 * HHALF + j];
        s_hid[node][j] = wmma::__float_to_tf32(fmaxf(v, 0.0f));
    }
    __syncthreads();

    int warp = t >> 5;
    int msub = warp & 3;
    int nbase = (warp >> 2) * 8;

    wmma::fragment<wmma::accumulator, 16, 16, 8, float> cf[8];
#pragma unroll
    for (int i = 0; i < 8; i++)
        wmma::load_matrix_sync(cf[i], g_b2rep + (nbase + i) * 16, HID, wmma::mem_row_major);

    for (int k = 0; k < 16; k++) {
        wmma::fragment<wmma::matrix_a, 16, 16, 8, wmma::precision::tf32, wmma::row_major> af;
        wmma::load_matrix_sync(af, &s_hid[msub * 16][k * 8], HHALF);
#pragma unroll
        for (int i = 0; i < 8; i++) {
            wmma::fragment<wmma::matrix_b, 16, 16, 8, wmma::precision::tf32, wmma::row_major> bf;
            wmma::load_matrix_sync(bf, w2 + (k * 8) * HID + (nbase + i) * 16, HID);
#pragma unroll
            for (int e = 0; e < bf.num_elements; e++) bf.x[e] = wmma::__float_to_tf32(bf.x[e]);
            wmma::mma_sync(cf[i], af, bf, cf[i]);
        }
    }
#pragma unroll
    for (int i = 0; i < 8; i++)
        wmma::store_matrix_sync(out + (n0 + msub * 16) * HID + (nbase + i) * 16,
                                cf[i], HID, wmma::mem_row_major);
}

// ---------------- launch (PDL-chained) --------------------------------------
template <typename K, typename... Args>
static void pdl_launch(K kern, dim3 grid, dim3 block, Args... args) {
    cudaLaunchConfig_t cfg = {};
    cfg.gridDim = grid;
    cfg.blockDim = block;
    cudaLaunchAttribute attr[1];
    attr[0].id = cudaLaunchAttributeProgrammaticStreamSerialization;
    attr[0].val.programmaticStreamSerializationAllowed = 1;
    cfg.attrs = attr;
    cfg.numAttrs = 1;
    cudaLaunchKernelEx(&cfg, kern, args...);
}

extern "C" void kernel_launch(void* const* d_in, const int* in_sizes, int n_in,
                              void* d_out, int out_size) {
    const float*  x      = (const float*)d_in[0];
    const int*    ei     = (const int*)d_in[1];
    const float2* coords = (const float2*)d_in[2];
    const float*  w1     = (const float*)d_in[3];
    const float*  b1     = (const float*)d_in[4];
    const float*  w2     = (const float*)d_in[5];
    const float*  b2     = (const float*)d_in[6];
    float*        out    = (float*)d_out;

    const int* row = ei;
    const int* col = ei + N_EDGES;

    pdl_launch(k_count, dim3(3137), dim3(256), coords, row, col, (const float4*)x, b2);
    pdl_launch(k_scan_cells, dim3(1), dim3(512));
    pdl_launch(k_fills, dim3(64), dim3(256), coords);
    pdl_launch(k_den_fvar, dim3(64 + 2048), dim3(256), (const float4*)x);
    pdl_launch(k_mlp, dim3(N_NODES / NPB), dim3(256), w1, b1, w2, out);
}